// round 1
// baseline (speedup 1.0000x reference)
#include <cuda_runtime.h>
#include <cuda_bf16.h>
#include <cstddef>
#include <math.h>

// ---------------- problem constants ----------------
#define Lc   4
#define Hc   2048
#define NHc  16
#define NKVc 4
#define DHc  128
#define Fc   5632
#define Rc   16
#define Bc   4
#define Sc   512
#define NCc  2
#define MTc  (Bc * Sc)          // 2048 tokens
#define LORA_SCALE 2.0f         // 32/16
#define INV_SQRT_DH 0.08838834764831845f

// ---------------- scratch (static device memory; allocation-free) ----------------
__device__ float d_h[MTc * Hc];
__device__ float d_x[MTc * Hc];
__device__ float d_q[MTc * NHc * DHc];
__device__ float d_k[MTc * NKVc * DHc];
__device__ float d_v[MTc * NKVc * DHc];
__device__ float d_t[MTc * Rc];
__device__ float d_y[MTc * Hc];
__device__ float d_sc[Bc * NHc * Sc * Sc];   // 16.8M floats
__device__ float d_ctx[MTc * NHc * DHc];
__device__ float d_g[MTc * Fc];
__device__ float d_u[MTc * Fc];
__device__ float d_pooled[Bc * Hc];
__device__ float d_cls[Bc * Hc];

// ---------------- embedding gather ----------------
__global__ void embed_kernel(const int* __restrict__ ids,
                             const float* __restrict__ emb,
                             float* __restrict__ h) {
    int row = blockIdx.x;
    const float* src = emb + (size_t)ids[row] * Hc;
    float* dst = h + (size_t)row * Hc;
    for (int i = threadIdx.x; i < Hc; i += 256) dst[i] = src[i];
}

// ---------------- rmsnorm (block per token row) ----------------
__global__ void rmsnorm_kernel(const float* __restrict__ in,
                               const float* __restrict__ w,
                               float* __restrict__ out) {
    int row = blockIdx.x;
    const float* x = in + (size_t)row * Hc;
    float ss = 0.f;
    for (int i = threadIdx.x; i < Hc; i += 256) { float v = x[i]; ss += v * v; }
    __shared__ float sh[256];
    sh[threadIdx.x] = ss; __syncthreads();
    for (int o = 128; o; o >>= 1) { if (threadIdx.x < o) sh[threadIdx.x] += sh[threadIdx.x + o]; __syncthreads(); }
    float sc = rsqrtf(sh[0] / (float)Hc + 1e-6f);
    float* y = out + (size_t)row * Hc;
    for (int i = threadIdx.x; i < Hc; i += 256) y[i] = x[i] * sc * w[i];
}

// ---------------- main SGEMM: C = A(MxK) * B(KxN) + bias, all dims %128==0 (K%8==0) ----------------
__global__ __launch_bounds__(256) void sgemm128(const float* __restrict__ A,
                                                const float* __restrict__ B,
                                                const float* __restrict__ bias,
                                                float* __restrict__ C,
                                                int M, int N, int K) {
    __shared__ float As[8][128];
    __shared__ float Bs[8][128];
    int tid = threadIdx.x;
    int bm = blockIdx.y * 128, bn = blockIdx.x * 128;
    int a_row = tid >> 1, a_col = (tid & 1) * 4;
    int b_row = tid >> 5, b_col = (tid & 31) * 4;
    int tx = tid & 15, ty = tid >> 4;
    float acc[8][8];
    #pragma unroll
    for (int i = 0; i < 8; i++)
        #pragma unroll
        for (int j = 0; j < 8; j++) acc[i][j] = 0.f;

    const float* Ap = A + (size_t)bm * K;
    const float* Bp = B + bn;

    for (int k0 = 0; k0 < K; k0 += 8) {
        float4 av = *(const float4*)(Ap + (size_t)a_row * K + k0 + a_col);
        As[a_col + 0][a_row] = av.x;
        As[a_col + 1][a_row] = av.y;
        As[a_col + 2][a_row] = av.z;
        As[a_col + 3][a_row] = av.w;
        float4 bv = *(const float4*)(Bp + (size_t)(k0 + b_row) * N + b_col);
        *(float4*)(&Bs[b_row][b_col]) = bv;
        __syncthreads();
        #pragma unroll
        for (int kk = 0; kk < 8; kk++) {
            float ar[8], br[8];
            #pragma unroll
            for (int i = 0; i < 8; i++) ar[i] = As[kk][ty * 8 + i];
            #pragma unroll
            for (int j = 0; j < 8; j++) br[j] = Bs[kk][tx * 8 + j];
            #pragma unroll
            for (int i = 0; i < 8; i++)
                #pragma unroll
                for (int j = 0; j < 8; j++) acc[i][j] += ar[i] * br[j];
        }
        __syncthreads();
    }
    #pragma unroll
    for (int i = 0; i < 8; i++) {
        int row = bm + ty * 8 + i;
        #pragma unroll
        for (int j = 0; j < 8; j += 4) {
            int col = bn + tx * 8 + j;
            float4 o;
            float b0 = bias ? bias[col + 0] : 0.f;
            float b1 = bias ? bias[col + 1] : 0.f;
            float b2 = bias ? bias[col + 2] : 0.f;
            float b3 = bias ? bias[col + 3] : 0.f;
            o.x = acc[i][j + 0] + b0;
            o.y = acc[i][j + 1] + b1;
            o.z = acc[i][j + 2] + b2;
            o.w = acc[i][j + 3] + b3;
            *(float4*)(C + (size_t)row * N + col) = o;
        }
    }
}

// ---------------- LoRA down: t[m,r] = sum_k x[m,k]*A[r,k]  (A row-major [R,K]) ----------------
__global__ void lora_down_kernel(const float* __restrict__ x,
                                 const float* __restrict__ A,
                                 float* __restrict__ t, int K) {
    int m = blockIdx.x;
    int r = threadIdx.y;          // 0..15
    int lane = threadIdx.x;       // 0..31
    const float* xr = x + (size_t)m * K;
    const float* Ar = A + (size_t)r * K;
    float acc = 0.f;
    for (int k = lane; k < K; k += 32) acc += xr[k] * Ar[k];
    #pragma unroll
    for (int o = 16; o; o >>= 1) acc += __shfl_xor_sync(0xFFFFFFFFu, acc, o);
    if (lane == 0) t[m * Rc + r] = acc;
}

// ---------------- LoRA up: y[m,n] += scale * sum_r t[m,r]*Bm[n,r]  (Bm [N,R]) ----------------
__global__ void lora_up_kernel(const float* __restrict__ t,
                               const float* __restrict__ Bm,
                               float* __restrict__ y, int N) {
    int n = blockIdx.x * 256 + threadIdx.x;
    int m = blockIdx.y;
    const float* tm = t + (size_t)m * Rc;
    const float* br = Bm + (size_t)n * Rc;
    float acc = 0.f;
    #pragma unroll
    for (int r = 0; r < Rc; r++) acc += tm[r] * br[r];
    y[(size_t)m * N + n] += LORA_SCALE * acc;
}

// ---------------- RoPE (rotate_half), in place ----------------
__global__ void rope_kernel(float* __restrict__ buf, int nheads) {
    int token = blockIdx.x;
    int head  = blockIdx.y;
    int d = threadIdx.x;           // 0..63
    int s = token % Sc;
    float* p = buf + ((size_t)token * nheads + head) * DHc;
    float freq = powf(1000000.0f, -(float)d / 64.0f);
    float ang = (float)s * freq;
    float sn, cs;
    sincosf(ang, &sn, &cs);
    float x1 = p[d], x2 = p[d + 64];
    p[d]      = x1 * cs - x2 * sn;
    p[d + 64] = x2 * cs + x1 * sn;
}

// ---------------- attention scores: per (b,h): S = Q K^T / sqrt(DH) ----------------
__global__ __launch_bounds__(256) void attn_scores_kernel(const float* __restrict__ qb,
                                                          const float* __restrict__ kb,
                                                          float* __restrict__ scores) {
    int bh = blockIdx.z;
    int b = bh / NHc, hd = bh % NHc;
    const float* A  = qb + ((size_t)b * Sc * NHc + hd) * DHc;            // lda = NHc*DHc
    const float* Bm = kb + ((size_t)b * Sc * NKVc + hd / (NHc / NKVc)) * DHc; // ldb = NKVc*DHc
    float* C = scores + (size_t)bh * Sc * Sc;
    const int lda = NHc * DHc, ldb = NKVc * DHc;
    int bm = blockIdx.y * 64, bn = blockIdx.x * 64;
    __shared__ float As[16][64];
    __shared__ float Bs[16][64];
    int tid = threadIdx.x;
    int lr = tid >> 2, lc = (tid & 3) * 4;
    int tx = tid & 15, ty = tid >> 4;
    float acc[4][4];
    #pragma unroll
    for (int i = 0; i < 4; i++)
        #pragma unroll
        for (int j = 0; j < 4; j++) acc[i][j] = 0.f;

    for (int k0 = 0; k0 < DHc; k0 += 16) {
        float4 av = *(const float4*)(A + (size_t)(bm + lr) * lda + k0 + lc);
        As[lc + 0][lr] = av.x; As[lc + 1][lr] = av.y; As[lc + 2][lr] = av.z; As[lc + 3][lr] = av.w;
        float4 bv = *(const float4*)(Bm + (size_t)(bn + lr) * ldb + k0 + lc);
        Bs[lc + 0][lr] = bv.x; Bs[lc + 1][lr] = bv.y; Bs[lc + 2][lr] = bv.z; Bs[lc + 3][lr] = bv.w;
        __syncthreads();
        #pragma unroll
        for (int kk = 0; kk < 16; kk++) {
            float ar[4], br[4];
            #pragma unroll
            for (int i = 0; i < 4; i++) ar[i] = As[kk][ty * 4 + i];
            #pragma unroll
            for (int j = 0; j < 4; j++) br[j] = Bs[kk][tx * 4 + j];
            #pragma unroll
            for (int i = 0; i < 4; i++)
                #pragma unroll
                for (int j = 0; j < 4; j++) acc[i][j] += ar[i] * br[j];
        }
        __syncthreads();
    }
    #pragma unroll
    for (int i = 0; i < 4; i++)
        #pragma unroll
        for (int j = 0; j < 4; j++)
            C[(size_t)(bm + ty * 4 + i) * Sc + bn + tx * 4 + j] = acc[i][j] * INV_SQRT_DH;
}

// ---------------- masked softmax over last dim (block per score row) ----------------
__global__ void softmax_kernel(float* __restrict__ scores, const int* __restrict__ mask) {
    int row = blockIdx.x;                   // b*NH*S + h*S + q
    int qpos = row % Sc;
    int b = row / (NHc * Sc);
    float* r = scores + (size_t)row * Sc;
    int t = threadIdx.x;                    // 128 threads, 4 keys each
    float v[4];
    float mx = -3.0e38f;
    #pragma unroll
    for (int i = 0; i < 4; i++) {
        int k = t + 128 * i;
        bool ok = (k <= qpos) && (mask[b * Sc + k] > 0);
        v[i] = ok ? r[k] : -1e30f;
        mx = fmaxf(mx, v[i]);
    }
    __shared__ float sh[128];
    sh[t] = mx; __syncthreads();
    for (int o = 64; o; o >>= 1) { if (t < o) sh[t] = fmaxf(sh[t], sh[t + o]); __syncthreads(); }
    mx = sh[0]; __syncthreads();
    float sm = 0.f;
    #pragma unroll
    for (int i = 0; i < 4; i++) { v[i] = expf(v[i] - mx); sm += v[i]; }
    sh[t] = sm; __syncthreads();
    for (int o = 64; o; o >>= 1) { if (t < o) sh[t] += sh[t + o]; __syncthreads(); }
    float inv = 1.0f / sh[0];
    #pragma unroll
    for (int i = 0; i < 4; i++) r[t + 128 * i] = v[i] * inv;
}

// ---------------- attention context: ctx = P V  per (b,h) ----------------
__global__ __launch_bounds__(256) void attn_ctx_kernel(const float* __restrict__ scores,
                                                       const float* __restrict__ vb,
                                                       float* __restrict__ ctx) {
    int bh = blockIdx.z;
    int b = bh / NHc, hd = bh % NHc;
    const float* A  = scores + (size_t)bh * Sc * Sc;                        // lda = Sc
    const float* Bm = vb + ((size_t)b * Sc * NKVc + hd / (NHc / NKVc)) * DHc; // ldb = 512
    float* C = ctx + ((size_t)b * Sc * NHc + hd) * DHc;                      // ldc = 2048
    const int ldb = NKVc * DHc, ldc = NHc * DHc;
    int bm = blockIdx.y * 64, bn = blockIdx.x * 64;
    __shared__ float As[16][64];
    __shared__ float Bs[16][64];
    int tid = threadIdx.x;
    int tx = tid & 15, ty = tid >> 4;
    float acc[4][4];
    #pragma unroll
    for (int i = 0; i < 4; i++)
        #pragma unroll
        for (int j = 0; j < 4; j++) acc[i][j] = 0.f;

    for (int k0 = 0; k0 < Sc; k0 += 16) {
        int lr = tid >> 2, lc = (tid & 3) * 4;
        float4 av = *(const float4*)(A + (size_t)(bm + lr) * Sc + k0 + lc);
        As[lc + 0][lr] = av.x; As[lc + 1][lr] = av.y; As[lc + 2][lr] = av.z; As[lc + 3][lr] = av.w;
        int kr = tid >> 4, nc = (tid & 15) * 4;
        float4 bv = *(const float4*)(Bm + (size_t)(k0 + kr) * ldb + bn + nc);
        *(float4*)(&Bs[kr][nc]) = bv;
        __syncthreads();
        #pragma unroll
        for (int kk = 0; kk < 16; kk++) {
            float ar[4], br[4];
            #pragma unroll
            for (int i = 0; i < 4; i++) ar[i] = As[kk][ty * 4 + i];
            #pragma unroll
            for (int j = 0; j < 4; j++) br[j] = Bs[kk][tx * 4 + j];
            #pragma unroll
            for (int i = 0; i < 4; i++)
                #pragma unroll
                for (int j = 0; j < 4; j++) acc[i][j] += ar[i] * br[j];
        }
        __syncthreads();
    }
    #pragma unroll
    for (int i = 0; i < 4; i++)
        #pragma unroll
        for (int j = 0; j < 4; j++)
            C[(size_t)(bm + ty * 4 + i) * ldc + bn + tx * 4 + j] = acc[i][j];
}

// ---------------- elementwise helpers ----------------
__global__ void add_kernel(float* __restrict__ a, const float* __restrict__ b, int n) {
    int i = blockIdx.x * 256 + threadIdx.x;
    if (i < n) a[i] += b[i];
}

__global__ void silu_mul_kernel(float* __restrict__ g, const float* __restrict__ u, int n) {
    int i = blockIdx.x * 256 + threadIdx.x;
    if (i < n) {
        float x = g[i];
        g[i] = (x / (1.0f + expf(-x))) * u[i];
    }
}

// ---------------- final pooling + rmsnorm(lnf) ----------------
__global__ void pool_kernel(const float* __restrict__ h, const int* __restrict__ mask,
                            const float* __restrict__ lnf, float* __restrict__ pooled) {
    int b = blockIdx.x;
    int t = threadIdx.x; // 256
    __shared__ float sh[256];
    int cnt = 0;
    for (int i = t; i < Sc; i += 256) cnt += mask[b * Sc + i];
    sh[t] = (float)cnt; __syncthreads();
    for (int o = 128; o; o >>= 1) { if (t < o) sh[t] += sh[t + o]; __syncthreads(); }
    int last = (int)sh[0] - 1;
    __syncthreads();
    const float* row = h + ((size_t)b * Sc + last) * Hc;
    float ss = 0.f;
    for (int i = t; i < Hc; i += 256) { float x = row[i]; ss += x * x; }
    sh[t] = ss; __syncthreads();
    for (int o = 128; o; o >>= 1) { if (t < o) sh[t] += sh[t + o]; __syncthreads(); }
    float sc = rsqrtf(sh[0] / (float)Hc + 1e-6f);
    for (int i = t; i < Hc; i += 256) pooled[b * Hc + i] = row[i] * sc * lnf[i];
}

// ---------------- classifier ----------------
__global__ void cls1_kernel(const float* __restrict__ pooled, const float* __restrict__ cw1,
                            const float* __restrict__ cb1, float* __restrict__ hid) {
    int n = blockIdx.x * 128 + threadIdx.x;
    int b = blockIdx.y;
    float acc = cb1[n];
    const float* p = pooled + (size_t)b * Hc;
    for (int k = 0; k < Hc; k++) acc += p[k] * cw1[(size_t)k * Hc + n];
    hid[(size_t)b * Hc + n] = fmaxf(acc, 0.f);
}

__global__ void cls2_kernel(const float* __restrict__ hid, const float* __restrict__ cw2,
                            const float* __restrict__ cb2, float* __restrict__ out) {
    int b = blockIdx.x >> 1, c = blockIdx.x & 1;
    float acc = 0.f;
    for (int k = threadIdx.x; k < Hc; k += 128) acc += hid[(size_t)b * Hc + k] * cw2[k * NCc + c];
    __shared__ float sh[128];
    sh[threadIdx.x] = acc; __syncthreads();
    for (int o = 64; o; o >>= 1) { if (threadIdx.x < o) sh[threadIdx.x] += sh[threadIdx.x + o]; __syncthreads(); }
    if (threadIdx.x == 0) out[b * NCc + c] = sh[0] + cb2[c];
}

// ---------------- host orchestration ----------------
extern "C" void kernel_launch(void* const* d_in, const int* in_sizes, int n_in,
                              void* d_out, int out_size) {
    (void)in_sizes; (void)n_in; (void)out_size;
    const int*   ids   = (const int*)d_in[0];
    const int*   mask  = (const int*)d_in[1];
    const float* embed = (const float*)d_in[2];
    const float* ln1   = (const float*)d_in[3];
    const float* wq    = (const float*)d_in[4];
    const float* bq    = (const float*)d_in[5];
    const float* wk    = (const float*)d_in[6];
    const float* bk    = (const float*)d_in[7];
    const float* wv    = (const float*)d_in[8];
    const float* bv    = (const float*)d_in[9];
    const float* wo    = (const float*)d_in[10];
    const float* laq   = (const float*)d_in[11];
    const float* lbq   = (const float*)d_in[12];
    const float* lak   = (const float*)d_in[13];
    const float* lbk   = (const float*)d_in[14];
    const float* lav   = (const float*)d_in[15];
    const float* lbv   = (const float*)d_in[16];
    const float* lao   = (const float*)d_in[17];
    const float* lbo   = (const float*)d_in[18];
    const float* ln2   = (const float*)d_in[19];
    const float* wg    = (const float*)d_in[20];
    const float* wu    = (const float*)d_in[21];
    const float* wd    = (const float*)d_in[22];
    const float* lnf   = (const float*)d_in[23];
    const float* cw1   = (const float*)d_in[24];
    const float* cb1   = (const float*)d_in[25];
    const float* cw2   = (const float*)d_in[26];
    const float* cb2   = (const float*)d_in[27];
    float* out = (float*)d_out;

    float *h, *x, *q, *k, *v, *t, *y, *sc, *ctx, *g, *u, *pooled, *cls;
    cudaGetSymbolAddress((void**)&h,   d_h);
    cudaGetSymbolAddress((void**)&x,   d_x);
    cudaGetSymbolAddress((void**)&q,   d_q);
    cudaGetSymbolAddress((void**)&k,   d_k);
    cudaGetSymbolAddress((void**)&v,   d_v);
    cudaGetSymbolAddress((void**)&t,   d_t);
    cudaGetSymbolAddress((void**)&y,   d_y);
    cudaGetSymbolAddress((void**)&sc,  d_sc);
    cudaGetSymbolAddress((void**)&ctx, d_ctx);
    cudaGetSymbolAddress((void**)&g,   d_g);
    cudaGetSymbolAddress((void**)&u,   d_u);
    cudaGetSymbolAddress((void**)&pooled, d_pooled);
    cudaGetSymbolAddress((void**)&cls,    d_cls);

    const int QN = NHc * DHc;    // 2048
    const int KN = NKVc * DHc;   // 512

    embed_kernel<<<MTc, 256>>>(ids, embed, h);

    for (int l = 0; l < Lc; l++) {
        const float* LN1 = ln1 + (size_t)l * Hc;
        const float* WQ = wq + (size_t)l * Hc * QN;  const float* BQ = bq + (size_t)l * QN;
        const float* WK = wk + (size_t)l * Hc * KN;  const float* BK = bk + (size_t)l * KN;
        const float* WV = wv + (size_t)l * Hc * KN;  const float* BV = bv + (size_t)l * KN;
        const float* WO = wo + (size_t)l * QN * Hc;
        const float* LAQ = laq + (size_t)l * Rc * Hc; const float* LBQ = lbq + (size_t)l * QN * Rc;
        const float* LAK = lak + (size_t)l * Rc * Hc; const float* LBK = lbk + (size_t)l * KN * Rc;
        const float* LAV = lav + (size_t)l * Rc * Hc; const float* LBV = lbv + (size_t)l * KN * Rc;
        const float* LAO = lao + (size_t)l * Rc * QN; const float* LBO = lbo + (size_t)l * Hc * Rc;
        const float* LN2 = ln2 + (size_t)l * Hc;
        const float* WG = wg + (size_t)l * Hc * Fc;
        const float* WU = wu + (size_t)l * Hc * Fc;
        const float* WD = wd + (size_t)l * Fc * Hc;

        // x = rmsnorm(h, ln1)
        rmsnorm_kernel<<<MTc, 256>>>(h, LN1, x);

        // Q
        lora_down_kernel<<<MTc, dim3(32, 16)>>>(x, LAQ, t, Hc);
        sgemm128<<<dim3(QN / 128, MTc / 128), 256>>>(x, WQ, BQ, q, MTc, QN, Hc);
        lora_up_kernel<<<dim3(QN / 256, MTc), 256>>>(t, LBQ, q, QN);
        // K
        lora_down_kernel<<<MTc, dim3(32, 16)>>>(x, LAK, t, Hc);
        sgemm128<<<dim3(KN / 128, MTc / 128), 256>>>(x, WK, BK, k, MTc, KN, Hc);
        lora_up_kernel<<<dim3(KN / 256, MTc), 256>>>(t, LBK, k, KN);
        // V
        lora_down_kernel<<<MTc, dim3(32, 16)>>>(x, LAV, t, Hc);
        sgemm128<<<dim3(KN / 128, MTc / 128), 256>>>(x, WV, BV, v, MTc, KN, Hc);
        lora_up_kernel<<<dim3(KN / 256, MTc), 256>>>(t, LBV, v, KN);

        // RoPE
        rope_kernel<<<dim3(MTc, NHc), 64>>>(q, NHc);
        rope_kernel<<<dim3(MTc, NKVc), 64>>>(k, NKVc);

        // attention
        attn_scores_kernel<<<dim3(Sc / 64, Sc / 64, Bc * NHc), 256>>>(q, k, sc);
        softmax_kernel<<<Bc * NHc * Sc, 128>>>(sc, mask);
        attn_ctx_kernel<<<dim3(DHc / 64, Sc / 64, Bc * NHc), 256>>>(sc, v, ctx);

        // O projection + LoRA + residual
        lora_down_kernel<<<MTc, dim3(32, 16)>>>(ctx, LAO, t, QN);
        sgemm128<<<dim3(Hc / 128, MTc / 128), 256>>>(ctx, WO, nullptr, y, MTc, Hc, QN);
        lora_up_kernel<<<dim3(Hc / 256, MTc), 256>>>(t, LBO, y, Hc);
        add_kernel<<<(MTc * Hc) / 256, 256>>>(h, y, MTc * Hc);

        // MLP
        rmsnorm_kernel<<<MTc, 256>>>(h, LN2, x);
        sgemm128<<<dim3(Fc / 128, MTc / 128), 256>>>(x, WG, nullptr, g, MTc, Fc, Hc);
        sgemm128<<<dim3(Fc / 128, MTc / 128), 256>>>(x, WU, nullptr, u, MTc, Fc, Hc);
        silu_mul_kernel<<<(MTc * Fc) / 256, 256>>>(g, u, MTc * Fc);
        sgemm128<<<dim3(Hc / 128, MTc / 128), 256>>>(g, WD, nullptr, y, MTc, Hc, Fc);
        add_kernel<<<(MTc * Hc) / 256, 256>>>(h, y, MTc * Hc);
    }

    // final norm + pooling + classifier
    pool_kernel<<<Bc, 256>>>(h, mask, lnf, pooled);
    cls1_kernel<<<dim3(Hc / 128, Bc), 128>>>(pooled, cw1, cb1, cls);
    cls2_kernel<<<Bc * NCc, 128>>>(cls, cw2, cb2, out);
}

// round 2
// speedup vs baseline: 2.4102x; 2.4102x over previous
#include <cuda_runtime.h>
#include <cuda_bf16.h>
#include <cstddef>
#include <cstdint>
#include <math.h>

// ---------------- problem constants ----------------
#define Lc   4
#define Hc   2048
#define NHc  16
#define NKVc 4
#define DHc  128
#define Fc   5632
#define Rc   16
#define Bc   4
#define Sc   512
#define NCc  2
#define MTc  (Bc * Sc)          // 2048 tokens
#define LORA_SCALE 2.0f         // 32/16
#define INV_SQRT_DH 0.08838834764831845f

// ---------------- scratch (static device memory; allocation-free) ----------------
__device__ float d_h[MTc * Hc];
__device__ float d_x[MTc * Hc];
__device__ float d_q[MTc * NHc * DHc];
__device__ float d_k[MTc * NKVc * DHc];
__device__ float d_v[MTc * NKVc * DHc];
__device__ float d_t[MTc * Rc];
__device__ float d_y[MTc * Hc];
__device__ float d_sc[Bc * NHc * Sc * Sc];
__device__ float d_ctx[MTc * NHc * DHc];
__device__ float d_g[MTc * Fc];
__device__ float d_u[MTc * Fc];
__device__ float d_pooled[Bc * Hc];
__device__ float d_cls[Bc * Hc];

// ---------------- helpers ----------------
__device__ __forceinline__ uint32_t f2tf32(float x) {
    uint32_t r;
    asm("cvt.rna.tf32.f32 %0, %1;" : "=r"(r) : "f"(x));
    return r;
}

__device__ __forceinline__ void mma_tf32(float* c, const uint32_t* a, const uint32_t* b) {
    asm volatile(
        "mma.sync.aligned.m16n8k8.row.col.f32.tf32.tf32.f32 "
        "{%0,%1,%2,%3}, {%4,%5,%6,%7}, {%8,%9}, {%0,%1,%2,%3};\n"
        : "+f"(c[0]), "+f"(c[1]), "+f"(c[2]), "+f"(c[3])
        : "r"(a[0]), "r"(a[1]), "r"(a[2]), "r"(a[3]), "r"(b[0]), "r"(b[1]));
}

// ---------------- embedding gather ----------------
__global__ void embed_kernel(const int* __restrict__ ids,
                             const float* __restrict__ emb,
                             float* __restrict__ h) {
    int row = blockIdx.x;
    const float* src = emb + (size_t)ids[row] * Hc;
    float* dst = h + (size_t)row * Hc;
    for (int i = threadIdx.x; i < Hc; i += 256) dst[i] = src[i];
}

// ---------------- rmsnorm (block per token row) ----------------
__global__ void rmsnorm_kernel(const float* __restrict__ in,
                               const float* __restrict__ w,
                               float* __restrict__ out) {
    int row = blockIdx.x;
    const float* x = in + (size_t)row * Hc;
    float ss = 0.f;
    for (int i = threadIdx.x; i < Hc; i += 256) { float v = x[i]; ss += v * v; }
    __shared__ float sh[256];
    sh[threadIdx.x] = ss; __syncthreads();
    for (int o = 128; o; o >>= 1) { if (threadIdx.x < o) sh[threadIdx.x] += sh[threadIdx.x + o]; __syncthreads(); }
    float sc = rsqrtf(sh[0] / (float)Hc + 1e-6f);
    float* y = out + (size_t)row * Hc;
    for (int i = threadIdx.x; i < Hc; i += 256) y[i] = x[i] * sc * w[i];
}

// ---------------- TF32 tensor-core GEMM: C = A(MxK,row) * B(KxN,row) + bias ----------------
// CTA tile 128x128, K-tile 32, 256 threads = 8 warps (4 along M x 2 along N),
// warp tile 32x64 = 2x8 grid of m16n8k8 mma.
// Smem: As[128][36] (row-major, pad 4) — A-frag LDS bank-free (grp*36+qd ≡ 4*grp+qd mod 32)
//       Bs[32][136] (row-major, pad 8) — B-frag LDS bank-free (qd*136+grp ≡ 8*qd+grp mod 32)
__global__ __launch_bounds__(256) void gemm_tf32(const float* __restrict__ A,
                                                 const float* __restrict__ B,
                                                 const float* __restrict__ bias,
                                                 float* __restrict__ C,
                                                 int M, int N, int K) {
    __shared__ uint32_t As[128 * 36];
    __shared__ uint32_t Bs[32 * 136];

    const int tid = threadIdx.x;
    const int bm = blockIdx.y * 128, bn = blockIdx.x * 128;
    const int warpId = tid >> 5, lane = tid & 31;
    const int warpM = warpId & 3, warpN = warpId >> 2;
    const int m0 = warpM * 32, n0 = warpN * 64;
    const int grp = lane >> 2, qd = lane & 3;

    // global load indices
    const int a_row = tid >> 3, a_col = (tid & 7) * 4;     // A: 4 iters of +32 rows
    const int b_row = tid >> 5, b_col = (tid & 31) * 4;    // B: 4 iters of +8 rows

    float acc[2][8][4];
    #pragma unroll
    for (int mt = 0; mt < 2; mt++)
        #pragma unroll
        for (int nt = 0; nt < 8; nt++)
            #pragma unroll
            for (int r = 0; r < 4; r++) acc[mt][nt][r] = 0.f;

    float4 pa[4], pb[4];
    const float* Ab = A + (size_t)bm * K;
    const float* Bb = B + bn;

    // prefetch k0 = 0
    #pragma unroll
    for (int i = 0; i < 4; i++) {
        pa[i] = *(const float4*)(Ab + (size_t)(a_row + 32 * i) * K + a_col);
        pb[i] = *(const float4*)(Bb + (size_t)(b_row + 8 * i) * N + b_col);
    }

    for (int k0 = 0; k0 < K; k0 += 32) {
        // store current tile (convert to tf32)
        #pragma unroll
        for (int i = 0; i < 4; i++) {
            uint32_t* asp = &As[(a_row + 32 * i) * 36 + a_col];
            asp[0] = f2tf32(pa[i].x); asp[1] = f2tf32(pa[i].y);
            asp[2] = f2tf32(pa[i].z); asp[3] = f2tf32(pa[i].w);
            uint32_t* bsp = &Bs[(b_row + 8 * i) * 136 + b_col];
            bsp[0] = f2tf32(pb[i].x); bsp[1] = f2tf32(pb[i].y);
            bsp[2] = f2tf32(pb[i].z); bsp[3] = f2tf32(pb[i].w);
        }
        __syncthreads();

        // prefetch next tile
        if (k0 + 32 < K) {
            #pragma unroll
            for (int i = 0; i < 4; i++) {
                pa[i] = *(const float4*)(Ab + (size_t)(a_row + 32 * i) * K + (k0 + 32) + a_col);
                pb[i] = *(const float4*)(Bb + (size_t)(k0 + 32 + b_row + 8 * i) * N + b_col);
            }
        }

        // compute 4 k-substeps of 8
        #pragma unroll
        for (int ks = 0; ks < 4; ks++) {
            uint32_t af[2][4], bf[8][2];
            #pragma unroll
            for (int mt = 0; mt < 2; mt++) {
                int mrow = m0 + mt * 16 + grp;
                af[mt][0] = As[(mrow)      * 36 + ks * 8 + qd];
                af[mt][1] = As[(mrow + 8)  * 36 + ks * 8 + qd];
                af[mt][2] = As[(mrow)      * 36 + ks * 8 + qd + 4];
                af[mt][3] = As[(mrow + 8)  * 36 + ks * 8 + qd + 4];
            }
            #pragma unroll
            for (int nt = 0; nt < 8; nt++) {
                int ncol = n0 + nt * 8 + grp;
                bf[nt][0] = Bs[(ks * 8 + qd)     * 136 + ncol];
                bf[nt][1] = Bs[(ks * 8 + qd + 4) * 136 + ncol];
            }
            #pragma unroll
            for (int mt = 0; mt < 2; mt++)
                #pragma unroll
                for (int nt = 0; nt < 8; nt++)
                    mma_tf32(acc[mt][nt], af[mt], bf[nt]);
        }
        __syncthreads();
    }

    // epilogue
    #pragma unroll
    for (int mt = 0; mt < 2; mt++) {
        int row = bm + m0 + mt * 16 + grp;
        #pragma unroll
        for (int nt = 0; nt < 8; nt++) {
            int col = bn + n0 + nt * 8 + 2 * qd;
            float b0 = bias ? bias[col] : 0.f;
            float b1 = bias ? bias[col + 1] : 0.f;
            float2 o0 = make_float2(acc[mt][nt][0] + b0, acc[mt][nt][1] + b1);
            float2 o1 = make_float2(acc[mt][nt][2] + b0, acc[mt][nt][3] + b1);
            *(float2*)(C + (size_t)row * N + col)       = o0;
            *(float2*)(C + (size_t)(row + 8) * N + col) = o1;
        }
    }
}

// ---------------- LoRA down: t[m,r] = sum_k x[m,k]*A[r,k] ----------------
__global__ void lora_down_kernel(const float* __restrict__ x,
                                 const float* __restrict__ A,
                                 float* __restrict__ t, int K) {
    int m = blockIdx.x;
    int r = threadIdx.y;
    int lane = threadIdx.x;
    const float* xr = x + (size_t)m * K;
    const float* Ar = A + (size_t)r * K;
    float acc = 0.f;
    for (int k = lane; k < K; k += 32) acc += xr[k] * Ar[k];
    #pragma unroll
    for (int o = 16; o; o >>= 1) acc += __shfl_xor_sync(0xFFFFFFFFu, acc, o);
    if (lane == 0) t[m * Rc + r] = acc;
}

// ---------------- LoRA up: y[m,n] += scale * sum_r t[m,r]*Bm[n,r] ----------------
__global__ void lora_up_kernel(const float* __restrict__ t,
                               const float* __restrict__ Bm,
                               float* __restrict__ y, int N) {
    int n = blockIdx.x * 256 + threadIdx.x;
    int m = blockIdx.y;
    const float* tm = t + (size_t)m * Rc;
    const float* br = Bm + (size_t)n * Rc;
    float acc = 0.f;
    #pragma unroll
    for (int r = 0; r < Rc; r++) acc += tm[r] * br[r];
    y[(size_t)m * N + n] += LORA_SCALE * acc;
}

// ---------------- RoPE (rotate_half), in place ----------------
__global__ void rope_kernel(float* __restrict__ buf, int nheads) {
    int token = blockIdx.x;
    int head  = blockIdx.y;
    int d = threadIdx.x;
    int s = token % Sc;
    float* p = buf + ((size_t)token * nheads + head) * DHc;
    float freq = powf(1000000.0f, -(float)d / 64.0f);
    float ang = (float)s * freq;
    float sn, cs;
    sincosf(ang, &sn, &cs);
    float x1 = p[d], x2 = p[d + 64];
    p[d]      = x1 * cs - x2 * sn;
    p[d + 64] = x2 * cs + x1 * sn;
}

// ---------------- attention scores: per (b,h): S = Q K^T / sqrt(DH) ----------------
__global__ __launch_bounds__(256) void attn_scores_kernel(const float* __restrict__ qb,
                                                          const float* __restrict__ kb,
                                                          float* __restrict__ scores) {
    int bh = blockIdx.z;
    int b = bh / NHc, hd = bh % NHc;
    const float* A  = qb + ((size_t)b * Sc * NHc + hd) * DHc;
    const float* Bm = kb + ((size_t)b * Sc * NKVc + hd / (NHc / NKVc)) * DHc;
    float* C = scores + (size_t)bh * Sc * Sc;
    const int lda = NHc * DHc, ldb = NKVc * DHc;
    int bm = blockIdx.y * 64, bn = blockIdx.x * 64;
    __shared__ float As[16][64];
    __shared__ float Bs[16][64];
    int tid = threadIdx.x;
    int lr = tid >> 2, lc = (tid & 3) * 4;
    int tx = tid & 15, ty = tid >> 4;
    float acc[4][4];
    #pragma unroll
    for (int i = 0; i < 4; i++)
        #pragma unroll
        for (int j = 0; j < 4; j++) acc[i][j] = 0.f;

    for (int k0 = 0; k0 < DHc; k0 += 16) {
        float4 av = *(const float4*)(A + (size_t)(bm + lr) * lda + k0 + lc);
        As[lc + 0][lr] = av.x; As[lc + 1][lr] = av.y; As[lc + 2][lr] = av.z; As[lc + 3][lr] = av.w;
        float4 bv = *(const float4*)(Bm + (size_t)(bn + lr) * ldb + k0 + lc);
        Bs[lc + 0][lr] = bv.x; Bs[lc + 1][lr] = bv.y; Bs[lc + 2][lr] = bv.z; Bs[lc + 3][lr] = bv.w;
        __syncthreads();
        #pragma unroll
        for (int kk = 0; kk < 16; kk++) {
            float ar[4], br[4];
            #pragma unroll
            for (int i = 0; i < 4; i++) ar[i] = As[kk][ty * 4 + i];
            #pragma unroll
            for (int j = 0; j < 4; j++) br[j] = Bs[kk][tx * 4 + j];
            #pragma unroll
            for (int i = 0; i < 4; i++)
                #pragma unroll
                for (int j = 0; j < 4; j++) acc[i][j] += ar[i] * br[j];
        }
        __syncthreads();
    }
    #pragma unroll
    for (int i = 0; i < 4; i++)
        #pragma unroll
        for (int j = 0; j < 4; j++)
            C[(size_t)(bm + ty * 4 + i) * Sc + bn + tx * 4 + j] = acc[i][j] * INV_SQRT_DH;
}

// ---------------- masked softmax ----------------
__global__ void softmax_kernel(float* __restrict__ scores, const int* __restrict__ mask) {
    int row = blockIdx.x;
    int qpos = row % Sc;
    int b = row / (NHc * Sc);
    float* r = scores + (size_t)row * Sc;
    int t = threadIdx.x;
    float v[4];
    float mx = -3.0e38f;
    #pragma unroll
    for (int i = 0; i < 4; i++) {
        int k = t + 128 * i;
        bool ok = (k <= qpos) && (mask[b * Sc + k] > 0);
        v[i] = ok ? r[k] : -1e30f;
        mx = fmaxf(mx, v[i]);
    }
    __shared__ float sh[128];
    sh[t] = mx; __syncthreads();
    for (int o = 64; o; o >>= 1) { if (t < o) sh[t] = fmaxf(sh[t], sh[t + o]); __syncthreads(); }
    mx = sh[0]; __syncthreads();
    float sm = 0.f;
    #pragma unroll
    for (int i = 0; i < 4; i++) { v[i] = expf(v[i] - mx); sm += v[i]; }
    sh[t] = sm; __syncthreads();
    for (int o = 64; o; o >>= 1) { if (t < o) sh[t] += sh[t + o]; __syncthreads(); }
    float inv = 1.0f / sh[0];
    #pragma unroll
    for (int i = 0; i < 4; i++) r[t + 128 * i] = v[i] * inv;
}

// ---------------- attention context: ctx = P V ----------------
__global__ __launch_bounds__(256) void attn_ctx_kernel(const float* __restrict__ scores,
                                                       const float* __restrict__ vb,
                                                       float* __restrict__ ctx) {
    int bh = blockIdx.z;
    int b = bh / NHc, hd = bh % NHc;
    const float* A  = scores + (size_t)bh * Sc * Sc;
    const float* Bm = vb + ((size_t)b * Sc * NKVc + hd / (NHc / NKVc)) * DHc;
    float* C = ctx + ((size_t)b * Sc * NHc + hd) * DHc;
    const int ldb = NKVc * DHc, ldc = NHc * DHc;
    int bm = blockIdx.y * 64, bn = blockIdx.x * 64;
    __shared__ float As[16][64];
    __shared__ float Bs[16][64];
    int tid = threadIdx.x;
    int tx = tid & 15, ty = tid >> 4;
    float acc[4][4];
    #pragma unroll
    for (int i = 0; i < 4; i++)
        #pragma unroll
        for (int j = 0; j < 4; j++) acc[i][j] = 0.f;

    for (int k0 = 0; k0 < Sc; k0 += 16) {
        int lr = tid >> 2, lc = (tid & 3) * 4;
        float4 av = *(const float4*)(A + (size_t)(bm + lr) * Sc + k0 + lc);
        As[lc + 0][lr] = av.x; As[lc + 1][lr] = av.y; As[lc + 2][lr] = av.z; As[lc + 3][lr] = av.w;
        int kr = tid >> 4, nc = (tid & 15) * 4;
        float4 bv = *(const float4*)(Bm + (size_t)(k0 + kr) * ldb + bn + nc);
        *(float4*)(&Bs[kr][nc]) = bv;
        __syncthreads();
        #pragma unroll
        for (int kk = 0; kk < 16; kk++) {
            float ar[4], br[4];
            #pragma unroll
            for (int i = 0; i < 4; i++) ar[i] = As[kk][ty * 4 + i];
            #pragma unroll
            for (int j = 0; j < 4; j++) br[j] = Bs[kk][tx * 4 + j];
            #pragma unroll
            for (int i = 0; i < 4; i++)
                #pragma unroll
                for (int j = 0; j < 4; j++) acc[i][j] += ar[i] * br[j];
        }
        __syncthreads();
    }
    #pragma unroll
    for (int i = 0; i < 4; i++)
        #pragma unroll
        for (int j = 0; j < 4; j++)
            C[(size_t)(bm + ty * 4 + i) * ldc + bn + tx * 4 + j] = acc[i][j];
}

// ---------------- elementwise helpers ----------------
__global__ void add_kernel(float* __restrict__ a, const float* __restrict__ b, int n) {
    int i = blockIdx.x * 256 + threadIdx.x;
    if (i < n) a[i] += b[i];
}

__global__ void silu_mul_kernel(float* __restrict__ g, const float* __restrict__ u, int n) {
    int i = blockIdx.x * 256 + threadIdx.x;
    if (i < n) {
        float x = g[i];
        g[i] = (x / (1.0f + expf(-x))) * u[i];
    }
}

// ---------------- final pooling + rmsnorm(lnf) ----------------
__global__ void pool_kernel(const float* __restrict__ h, const int* __restrict__ mask,
                            const float* __restrict__ lnf, float* __restrict__ pooled) {
    int b = blockIdx.x;
    int t = threadIdx.x;
    __shared__ float sh[256];
    int cnt = 0;
    for (int i = t; i < Sc; i += 256) cnt += mask[b * Sc + i];
    sh[t] = (float)cnt; __syncthreads();
    for (int o = 128; o; o >>= 1) { if (t < o) sh[t] += sh[t + o]; __syncthreads(); }
    int last = (int)sh[0] - 1;
    __syncthreads();
    const float* row = h + ((size_t)b * Sc + last) * Hc;
    float ss = 0.f;
    for (int i = t; i < Hc; i += 256) { float x = row[i]; ss += x * x; }
    sh[t] = ss; __syncthreads();
    for (int o = 128; o; o >>= 1) { if (t < o) sh[t] += sh[t + o]; __syncthreads(); }
    float sc = rsqrtf(sh[0] / (float)Hc + 1e-6f);
    for (int i = t; i < Hc; i += 256) pooled[b * Hc + i] = row[i] * sc * lnf[i];
}

// ---------------- classifier ----------------
__global__ void cls1_kernel(const float* __restrict__ pooled, const float* __restrict__ cw1,
                            const float* __restrict__ cb1, float* __restrict__ hid) {
    int n = blockIdx.x * 128 + threadIdx.x;
    int b = blockIdx.y;
    float acc = cb1[n];
    const float* p = pooled + (size_t)b * Hc;
    for (int k = 0; k < Hc; k++) acc += p[k] * cw1[(size_t)k * Hc + n];
    hid[(size_t)b * Hc + n] = fmaxf(acc, 0.f);
}

__global__ void cls2_kernel(const float* __restrict__ hid, const float* __restrict__ cw2,
                            const float* __restrict__ cb2, float* __restrict__ out) {
    int b = blockIdx.x >> 1, c = blockIdx.x & 1;
    float acc = 0.f;
    for (int k = threadIdx.x; k < Hc; k += 128) acc += hid[(size_t)b * Hc + k] * cw2[k * NCc + c];
    __shared__ float sh[128];
    sh[threadIdx.x] = acc; __syncthreads();
    for (int o = 64; o; o >>= 1) { if (threadIdx.x < o) sh[threadIdx.x] += sh[threadIdx.x + o]; __syncthreads(); }
    if (threadIdx.x == 0) out[b * NCc + c] = sh[0] + cb2[c];
}

// ---------------- host orchestration ----------------
extern "C" void kernel_launch(void* const* d_in, const int* in_sizes, int n_in,
                              void* d_out, int out_size) {
    (void)in_sizes; (void)n_in; (void)out_size;
    const int*   ids   = (const int*)d_in[0];
    const int*   mask  = (const int*)d_in[1];
    const float* embed = (const float*)d_in[2];
    const float* ln1   = (const float*)d_in[3];
    const float* wq    = (const float*)d_in[4];
    const float* bq    = (const float*)d_in[5];
    const float* wk    = (const float*)d_in[6];
    const float* bk    = (const float*)d_in[7];
    const float* wv    = (const float*)d_in[8];
    const float* bv    = (const float*)d_in[9];
    const float* wo    = (const float*)d_in[10];
    const float* laq   = (const float*)d_in[11];
    const float* lbq   = (const float*)d_in[12];
    const float* lak   = (const float*)d_in[13];
    const float* lbk   = (const float*)d_in[14];
    const float* lav   = (const float*)d_in[15];
    const float* lbv   = (const float*)d_in[16];
    const float* lao   = (const float*)d_in[17];
    const float* lbo   = (const float*)d_in[18];
    const float* ln2   = (const float*)d_in[19];
    const float* wg    = (const float*)d_in[20];
    const float* wu    = (const float*)d_in[21];
    const float* wd    = (const float*)d_in[22];
    const float* lnf   = (const float*)d_in[23];
    const float* cw1   = (const float*)d_in[24];
    const float* cb1   = (const float*)d_in[25];
    const float* cw2   = (const float*)d_in[26];
    const float* cb2   = (const float*)d_in[27];
    float* out = (float*)d_out;

    float *h, *x, *q, *k, *v, *t, *y, *sc, *ctx, *g, *u, *pooled, *cls;
    cudaGetSymbolAddress((void**)&h,   d_h);
    cudaGetSymbolAddress((void**)&x,   d_x);
    cudaGetSymbolAddress((void**)&q,   d_q);
    cudaGetSymbolAddress((void**)&k,   d_k);
    cudaGetSymbolAddress((void**)&v,   d_v);
    cudaGetSymbolAddress((void**)&t,   d_t);
    cudaGetSymbolAddress((void**)&y,   d_y);
    cudaGetSymbolAddress((void**)&sc,  d_sc);
    cudaGetSymbolAddress((void**)&ctx, d_ctx);
    cudaGetSymbolAddress((void**)&g,   d_g);
    cudaGetSymbolAddress((void**)&u,   d_u);
    cudaGetSymbolAddress((void**)&pooled, d_pooled);
    cudaGetSymbolAddress((void**)&cls,    d_cls);

    const int QN = NHc * DHc;    // 2048
    const int KN = NKVc * DHc;   // 512

    embed_kernel<<<MTc, 256>>>(ids, embed, h);

    for (int l = 0; l < Lc; l++) {
        const float* LN1 = ln1 + (size_t)l * Hc;
        const float* WQ = wq + (size_t)l * Hc * QN;  const float* BQ = bq + (size_t)l * QN;
        const float* WK = wk + (size_t)l * Hc * KN;  const float* BK = bk + (size_t)l * KN;
        const float* WV = wv + (size_t)l * Hc * KN;  const float* BV = bv + (size_t)l * KN;
        const float* WO = wo + (size_t)l * QN * Hc;
        const float* LAQ = laq + (size_t)l * Rc * Hc; const float* LBQ = lbq + (size_t)l * QN * Rc;
        const float* LAK = lak + (size_t)l * Rc * Hc; const float* LBK = lbk + (size_t)l * KN * Rc;
        const float* LAV = lav + (size_t)l * Rc * Hc; const float* LBV = lbv + (size_t)l * KN * Rc;
        const float* LAO = lao + (size_t)l * Rc * QN; const float* LBO = lbo + (size_t)l * Hc * Rc;
        const float* LN2 = ln2 + (size_t)l * Hc;
        const float* WG = wg + (size_t)l * Hc * Fc;
        const float* WU = wu + (size_t)l * Hc * Fc;
        const float* WD = wd + (size_t)l * Fc * Hc;

        rmsnorm_kernel<<<MTc, 256>>>(h, LN1, x);

        // Q
        lora_down_kernel<<<MTc, dim3(32, 16)>>>(x, LAQ, t, Hc);
        gemm_tf32<<<dim3(QN / 128, MTc / 128), 256>>>(x, WQ, BQ, q, MTc, QN, Hc);
        lora_up_kernel<<<dim3(QN / 256, MTc), 256>>>(t, LBQ, q, QN);
        // K
        lora_down_kernel<<<MTc, dim3(32, 16)>>>(x, LAK, t, Hc);
        gemm_tf32<<<dim3(KN / 128, MTc / 128), 256>>>(x, WK, BK, k, MTc, KN, Hc);
        lora_up_kernel<<<dim3(KN / 256, MTc), 256>>>(t, LBK, k, KN);
        // V
        lora_down_kernel<<<MTc, dim3(32, 16)>>>(x, LAV, t, Hc);
        gemm_tf32<<<dim3(KN / 128, MTc / 128), 256>>>(x, WV, BV, v, MTc, KN, Hc);
        lora_up_kernel<<<dim3(KN / 256, MTc), 256>>>(t, LBV, v, KN);

        // RoPE
        rope_kernel<<<dim3(MTc, NHc), 64>>>(q, NHc);
        rope_kernel<<<dim3(MTc, NKVc), 64>>>(k, NKVc);

        // attention
        attn_scores_kernel<<<dim3(Sc / 64, Sc / 64, Bc * NHc), 256>>>(q, k, sc);
        softmax_kernel<<<Bc * NHc * Sc, 128>>>(sc, mask);
        attn_ctx_kernel<<<dim3(DHc / 64, Sc / 64, Bc * NHc), 256>>>(sc, v, ctx);

        // O projection + LoRA + residual
        lora_down_kernel<<<MTc, dim3(32, 16)>>>(ctx, LAO, t, QN);
        gemm_tf32<<<dim3(Hc / 128, MTc / 128), 256>>>(ctx, WO, nullptr, y, MTc, Hc, QN);
        lora_up_kernel<<<dim3(Hc / 256, MTc), 256>>>(t, LBO, y, Hc);
        add_kernel<<<(MTc * Hc) / 256, 256>>>(h, y, MTc * Hc);

        // MLP
        rmsnorm_kernel<<<MTc, 256>>>(h, LN2, x);
        gemm_tf32<<<dim3(Fc / 128, MTc / 128), 256>>>(x, WG, nullptr, g, MTc, Fc, Hc);
        gemm_tf32<<<dim3(Fc / 128, MTc / 128), 256>>>(x, WU, nullptr, u, MTc, Fc, Hc);
        silu_mul_kernel<<<(MTc * Fc) / 256, 256>>>(g, u, MTc * Fc);
        gemm_tf32<<<dim3(Hc / 128, MTc / 128), 256>>>(g, WD, nullptr, y, MTc, Hc, Fc);
        add_kernel<<<(MTc * Hc) / 256, 256>>>(h, y, MTc * Hc);
    }

    pool_kernel<<<Bc, 256>>>(h, mask, lnf, pooled);
    cls1_kernel<<<dim3(Hc / 128, Bc), 128>>>(pooled, cw1, cb1, cls);
    cls2_kernel<<<Bc * NCc, 128>>>(cls, cw2, cb2, out);
}